// round 15
// baseline (speedup 1.0000x reference)
#include <cuda_runtime.h>
#include <cuda_fp16.h>
#include <cstdint>

#define NPAT 50000
#define NCON 20000
#define NN   70000
#define EE   800000
#define HH   128
#define LL   2

// ---------------- scratch (static device globals; no allocs allowed) ----------------
__device__ __half g_h0   [(size_t)NN * HH];   // proj output / layer-0 input
__device__ __half g_h1   [(size_t)NN * HH];   // layer-0 output / layer-1 input
__device__ __half g_agg16[(size_t)NN * HH];   // neighbor mean (fp32 accum, fp16 store)
__device__ int    g_deg [NN];
__device__ float  g_rcnt[NN];
__device__ int    g_off [NN + 1];
__device__ int    g_cur [NN];
__device__ int    g_csr [2 * EE];
// fp16 hi/lo split weights, half2-packed along k.
// Layer variant v occupies halves [v*65536, v*65536+32768) = hi, [+32768, +65536) = lo.
__device__ __half g_B16[(size_t)8 * 128 * 128 * 2];   // 4 variants x (hi+lo) x 32768
__device__ __half g_Bp16[2 * 64 * 128];               // W_p hi/lo (K=64)
__device__ __half g_Bc16[2 * 128 * 128];              // W_c hi/lo (K=128)

// ---------------- helpers ----------------
__device__ __forceinline__ void mma_f16(float* c, const uint32_t* a, const uint32_t* b) {
    asm volatile(
        "mma.sync.aligned.m16n8k16.row.col.f32.f16.f16.f32 "
        "{%0,%1,%2,%3}, {%4,%5,%6,%7}, {%8,%9}, {%0,%1,%2,%3};"
        : "+f"(c[0]), "+f"(c[1]), "+f"(c[2]), "+f"(c[3])
        : "r"(a[0]), "r"(a[1]), "r"(a[2]), "r"(a[3]),
          "r"(b[0]), "r"(b[1]));
}

// ---------------- degree histogram ----------------
__global__ void deg_kernel(const int* __restrict__ dst_pc, const int* __restrict__ dst_cp,
                           int* __restrict__ deg) {
    int i = blockIdx.x * blockDim.x + threadIdx.x;
    if (i < EE)               atomicAdd(&deg[NPAT + dst_pc[i]], 1);
    else if (i < 2 * EE)      atomicAdd(&deg[dst_cp[i - EE]], 1);
}

// ---------------- single-block exclusive scan (+ rcnt + cur zero) -------------------
__global__ void scan_kernel(const int* __restrict__ deg, int* __restrict__ off,
                            float* __restrict__ rcnt, int* __restrict__ cur) {
    __shared__ int ssum[1024];
    int tid = threadIdx.x;
    const int PER = (NN + 1023) / 1024;
    int base = tid * PER;
    int s = 0;
    for (int i = 0; i < PER; i++) { int idx = base + i; if (idx < NN) s += deg[idx]; }
    ssum[tid] = s;
    __syncthreads();
    for (int ofs = 1; ofs < 1024; ofs <<= 1) {
        int v = (tid >= ofs) ? ssum[tid - ofs] : 0;
        __syncthreads();
        ssum[tid] += v;
        __syncthreads();
    }
    int run = (tid == 0) ? 0 : ssum[tid - 1];
    for (int i = 0; i < PER; i++) {
        int idx = base + i;
        if (idx < NN) {
            int d = deg[idx];
            off[idx] = run; run += d;
            rcnt[idx] = 1.0f / (float)max(d, 1);
            cur[idx] = 0;
        }
    }
    if (tid == 0) off[NN] = ssum[1023];
}

// ---------------- CSR fill ----------------
__global__ void fill_kernel(const int* __restrict__ src_pc, const int* __restrict__ dst_pc,
                            const int* __restrict__ src_cp, const int* __restrict__ dst_cp,
                            const int* __restrict__ off, int* __restrict__ cur,
                            int* __restrict__ csr) {
    int i = blockIdx.x * blockDim.x + threadIdx.x;
    int s, d;
    if (i < EE)          { s = src_pc[i];             d = NPAT + dst_pc[i]; }
    else if (i < 2 * EE) { s = NPAT + src_cp[i - EE]; d = dst_cp[i - EE]; }
    else return;
    int pos = off[d] + atomicAdd(&cur[d], 1);
    csr[pos] = s;
}

// ---------------- fp16 gather-aggregate (fp32 accumulate, fp16 store) ---------------
__global__ void gather_kernel(const __half* __restrict__ X16,
                              const int* __restrict__ off, const int* __restrict__ csr,
                              const float* __restrict__ rcnt, __half* __restrict__ AGG16) {
    int warp = (int)((blockIdx.x * (long long)blockDim.x + threadIdx.x) >> 5);
    if (warp >= NN) return;
    int lane = threadIdx.x & 31;
    int beg = off[warp], end = off[warp + 1];
    float4 acc = make_float4(0.f, 0.f, 0.f, 0.f);
    int e = beg;
    for (; e + 32 <= end; e += 32) {
        int idx = csr[e + lane];
#pragma unroll
        for (int j = 0; j < 32; j++) {
            int s = __shfl_sync(0xffffffffu, idx, j);
            uint2 u = ((const uint2*)(X16 + (size_t)s * HH))[lane];
            float2 f0 = __half22float2(*(__half2*)&u.x);
            float2 f1 = __half22float2(*(__half2*)&u.y);
            acc.x += f0.x; acc.y += f0.y; acc.z += f1.x; acc.w += f1.y;
        }
    }
    int rem = end - e;
    if (rem > 0) {
        int idx = (lane < rem) ? csr[e + lane] : 0;
        for (int j = 0; j < rem; j++) {
            int s = __shfl_sync(0xffffffffu, idx, j);
            uint2 u = ((const uint2*)(X16 + (size_t)s * HH))[lane];
            float2 f0 = __half22float2(*(__half2*)&u.x);
            float2 f1 = __half22float2(*(__half2*)&u.y);
            acc.x += f0.x; acc.y += f0.y; acc.z += f1.x; acc.w += f1.y;
        }
    }
    float rc = rcnt[warp];
    uint2 o;
    *(__half2*)&o.x = __floats2half2_rn(acc.x * rc, acc.y * rc);
    *(__half2*)&o.y = __floats2half2_rn(acc.z * rc, acc.w * rc);
    ((uint2*)(AGG16 + (size_t)warp * HH))[lane] = o;
}

// ---------------- weight prep: fp16 hi/lo split, half2-packed along k ---------------
// ranges: [0,131072) layer variants; [131072,139264) W_p; [139264,155648) W_c
__global__ void prepB_kernel(const float* __restrict__ W_root, const float* __restrict__ W_rel,
                             const float* __restrict__ W_p, const float* __restrict__ W_c,
                             __half* __restrict__ B16, __half* __restrict__ Bp16,
                             __half* __restrict__ Bc16) {
    int i = blockIdx.x * blockDim.x + threadIdx.x;
    float val; int k, n;
    __half* dst; size_t stride_split;
    if (i < 131072) {
        int v = i >> 15, rem = i & 32767;
        k = rem >> 7; n = rem & 127;
        int l = v >> 1, type = v & 1;
        if (k < 128) val = W_root[((size_t)l * 128 + k) * 128 + n];
        else {
            int rel = (type == 0) ? 1 : 0;
            val = W_rel[(((size_t)l * 2 + rel) * 128 + (k - 128)) * 128 + n];
        }
        dst = B16 + (size_t)v * 65536;
        stride_split = 32768;
    } else if (i < 139264) {
        int rem = i - 131072;
        k = rem >> 7; n = rem & 127;
        val = W_p[k * 128 + n];
        dst = Bp16;
        stride_split = 8192;
    } else if (i < 155648) {
        int rem = i - 139264;
        k = rem >> 7; n = rem & 127;
        val = W_c[k * 128 + n];
        dst = Bc16;
        stride_split = 16384;
    } else return;
    __half hi = __float2half_rn(val);
    float lo = val - __half2float(hi);
    __half lo16 = __float2half_rn(lo);
    int k2 = k >> 1, kb = k & 1;
    size_t idx = ((size_t)k2 * 128 + n) * 2 + kb;
    dst[idx] = hi;
    dst[stride_split + idx] = lo16;
}

// ---------------- shared mma-tile smem layout ---------------------------------------
#define ASTR20  20
#define BSTR136 136
#define SM_A    0
#define SM_BH   (128 * ASTR20)                       // 2560
#define SM_BL   (128 * ASTR20 + 16 * BSTR136)        // 4736
#define SM_WORDS (128 * ASTR20 + 2 * 16 * BSTR136)   // 6912 words = 27648 B

// ---------------- projection MMA: CH[M,128] = fp16(A[M,K] @ W + b) -------------------
template <int KCH>
__global__ void __launch_bounds__(256, 2)
proj_mma_kernel(const float* __restrict__ A, const __half* __restrict__ Bsp,
                const float* __restrict__ bias, __half* __restrict__ CH, int M) {
    extern __shared__ uint32_t smu[];
    int tid = threadIdx.x, wid = tid >> 5, lane = tid & 31;
    int warpM = wid & 3, warpN = wid >> 2;
    int gid = lane >> 2, tig = lane & 3;
    const int K = KCH * 32;
    const int SPLIT_HALVES = KCH * 32 * 128;

    float acc[2][8][4];
#pragma unroll
    for (int mt = 0; mt < 2; mt++)
#pragma unroll
        for (int nt = 0; nt < 8; nt++)
#pragma unroll
            for (int r = 0; r < 4; r++) acc[mt][nt][r] = 0.f;

    int arow = tid >> 1;
    int lr = blockIdx.x * 128 + arow;
    bool valid = lr < M;
    int f4base = (tid & 1) * 4;

    const uint4* bh4 = (const uint4*)(Bsp);
    const uint4* bl4 = (const uint4*)(Bsp + SPLIT_HALVES);

#pragma unroll
    for (int chunk = 0; chunk < KCH; chunk++) {
        const float4* src4 = (const float4*)(A + (size_t)lr * K + chunk * 32);
#pragma unroll
        for (int i = 0; i < 4; i++) {
            int f4 = f4base + i;
            float4 a = valid ? src4[f4] : make_float4(0.f, 0.f, 0.f, 0.f);
            uint2 u;
            *(__half2*)&u.x = __floats2half2_rn(a.x, a.y);
            *(__half2*)&u.y = __floats2half2_rn(a.z, a.w);
            *(uint2*)&smu[SM_A + arow * ASTR20 + f4 * 2] = u;
        }
        {
            int gbase = chunk * 16 * 32;
#pragma unroll
            for (int i = 0; i < 2; i++) {
                int e = tid + 256 * i;
                int k2 = e >> 5, n4 = e & 31;
                uint4 uh = bh4[gbase + e];
                uint4 ul = bl4[gbase + e];
                *(uint4*)&smu[SM_BH + k2 * BSTR136 + n4 * 4] = uh;
                *(uint4*)&smu[SM_BL + k2 * BSTR136 + n4 * 4] = ul;
            }
        }
        __syncthreads();

#pragma unroll
        for (int step = 0; step < 2; step++) {
            int s8 = step * 8;
            uint32_t a[2][4];
#pragma unroll
            for (int mt = 0; mt < 2; mt++) {
                int r0 = warpM * 32 + mt * 16 + gid;
                a[mt][0] = smu[SM_A + r0 * ASTR20 + s8 + tig];
                a[mt][1] = smu[SM_A + (r0 + 8) * ASTR20 + s8 + tig];
                a[mt][2] = smu[SM_A + r0 * ASTR20 + s8 + 4 + tig];
                a[mt][3] = smu[SM_A + (r0 + 8) * ASTR20 + s8 + 4 + tig];
            }
#pragma unroll
            for (int nt = 0; nt < 8; nt++) {
                int n = warpN * 64 + nt * 8 + gid;
                uint32_t bh[2], bl[2];
                bh[0] = smu[SM_BH + (s8 + tig) * BSTR136 + n];
                bh[1] = smu[SM_BH + (s8 + 4 + tig) * BSTR136 + n];
                bl[0] = smu[SM_BL + (s8 + tig) * BSTR136 + n];
                bl[1] = smu[SM_BL + (s8 + 4 + tig) * BSTR136 + n];
#pragma unroll
                for (int mt = 0; mt < 2; mt++) {
                    mma_f16(acc[mt][nt], a[mt], bh);
                    mma_f16(acc[mt][nt], a[mt], bl);
                }
            }
        }
        __syncthreads();
    }

#pragma unroll
    for (int mt = 0; mt < 2; mt++) {
        int row = blockIdx.x * 128 + warpM * 32 + mt * 16 + gid;
#pragma unroll
        for (int nt = 0; nt < 8; nt++) {
            int col = warpN * 64 + nt * 8 + tig * 2;
            float2 bv = *(const float2*)&bias[col];
            if (row < M)
                *(__half2*)&CH[(size_t)row * HH + col] =
                    __floats2half2_rn(acc[mt][nt][0] + bv.x, acc[mt][nt][1] + bv.y);
            if (row + 8 < M)
                *(__half2*)&CH[(size_t)(row + 8) * HH + col] =
                    __floats2half2_rn(acc[mt][nt][2] + bv.x, acc[mt][nt][3] + bv.y);
        }
    }
}

// ---------------- mma.sync fp16 layer: out = relu([x|agg] @ (Bhi+Blo) + b) -----------
template <bool FINAL>
__global__ void __launch_bounds__(256, 2)
layer_mma_kernel(const __half* __restrict__ X16, const __half* __restrict__ AGG16,
                 const __half* __restrict__ B16, const float* __restrict__ bias,
                 float* __restrict__ C, __half* __restrict__ CH, int layer) {
    extern __shared__ uint32_t smu[];
    int tid = threadIdx.x, wid = tid >> 5, lane = tid & 31;
    int warpM = wid & 3, warpN = wid >> 2;
    int gid = lane >> 2, tig = lane & 3;

    const int NBP_T = (NPAT + 127) / 128;   // 391
    int bid = blockIdx.x;
    int base, rowlim, v;
    if (bid < NBP_T) { base = bid * 128;                  rowlim = NPAT; v = layer * 2; }
    else             { base = NPAT + (bid - NBP_T) * 128; rowlim = NN;   v = layer * 2 + 1; }

    float acc[2][8][4];
#pragma unroll
    for (int mt = 0; mt < 2; mt++)
#pragma unroll
        for (int nt = 0; nt < 8; nt++)
#pragma unroll
            for (int r = 0; r < 4; r++) acc[mt][nt][r] = 0.f;

    int arow = tid >> 1;
    int node = base + arow;
    bool valid = node < rowlim;
    int f4base = (tid & 1) * 4;

    const uint4* bh4 = (const uint4*)(B16 + (size_t)v * 65536);
    const uint4* bl4 = (const uint4*)(B16 + (size_t)v * 65536 + 32768);

    for (int chunk = 0; chunk < 8; chunk++) {
        const __half* src = (chunk < 4)
            ? (X16   + (size_t)node * HH + chunk * 32)
            : (AGG16 + (size_t)node * HH + (chunk - 4) * 32);
#pragma unroll
        for (int i = 0; i < 4; i++) {
            int f4 = f4base + i;
            uint2 u = valid ? ((const uint2*)src)[f4] : make_uint2(0u, 0u);
            *(uint2*)&smu[SM_A + arow * ASTR20 + f4 * 2] = u;
        }
        {
            int gbase = chunk * 16 * 32;
#pragma unroll
            for (int i = 0; i < 2; i++) {
                int e = tid + 256 * i;
                int k2 = e >> 5, n4 = e & 31;
                uint4 uh = bh4[gbase + e];
                uint4 ul = bl4[gbase + e];
                *(uint4*)&smu[SM_BH + k2 * BSTR136 + n4 * 4] = uh;
                *(uint4*)&smu[SM_BL + k2 * BSTR136 + n4 * 4] = ul;
            }
        }
        __syncthreads();

#pragma unroll
        for (int step = 0; step < 2; step++) {
            int s8 = step * 8;
            uint32_t a[2][4];
#pragma unroll
            for (int mt = 0; mt < 2; mt++) {
                int r0 = warpM * 32 + mt * 16 + gid;
                a[mt][0] = smu[SM_A + r0 * ASTR20 + s8 + tig];
                a[mt][1] = smu[SM_A + (r0 + 8) * ASTR20 + s8 + tig];
                a[mt][2] = smu[SM_A + r0 * ASTR20 + s8 + 4 + tig];
                a[mt][3] = smu[SM_A + (r0 + 8) * ASTR20 + s8 + 4 + tig];
            }
#pragma unroll
            for (int nt = 0; nt < 8; nt++) {
                int n = warpN * 64 + nt * 8 + gid;
                uint32_t bh[2], bl[2];
                bh[0] = smu[SM_BH + (s8 + tig) * BSTR136 + n];
                bh[1] = smu[SM_BH + (s8 + 4 + tig) * BSTR136 + n];
                bl[0] = smu[SM_BL + (s8 + tig) * BSTR136 + n];
                bl[1] = smu[SM_BL + (s8 + 4 + tig) * BSTR136 + n];
#pragma unroll
                for (int mt = 0; mt < 2; mt++) {
                    mma_f16(acc[mt][nt], a[mt], bh);
                    mma_f16(acc[mt][nt], a[mt], bl);
                }
            }
        }
        __syncthreads();
    }

#pragma unroll
    for (int mt = 0; mt < 2; mt++) {
        int row = base + warpM * 32 + mt * 16 + gid;
#pragma unroll
        for (int nt = 0; nt < 8; nt++) {
            int col = warpN * 64 + nt * 8 + tig * 2;
            float2 bv = *(const float2*)&bias[col];
            if (row < rowlim) {
                float2 o;
                o.x = fmaxf(acc[mt][nt][0] + bv.x, 0.f);
                o.y = fmaxf(acc[mt][nt][1] + bv.y, 0.f);
                if (FINAL) *(float2*)&C[(size_t)row * HH + col] = o;
                else       *(__half2*)&CH[(size_t)row * HH + col] = __floats2half2_rn(o.x, o.y);
            }
            if (row + 8 < rowlim) {
                float2 o;
                o.x = fmaxf(acc[mt][nt][2] + bv.x, 0.f);
                o.y = fmaxf(acc[mt][nt][3] + bv.y, 0.f);
                if (FINAL) *(float2*)&C[(size_t)(row + 8) * HH + col] = o;
                else       *(__half2*)&CH[(size_t)(row + 8) * HH + col] = __floats2half2_rn(o.x, o.y);
            }
        }
    }
}

// ---------------- launch ----------------
extern "C" void kernel_launch(void* const* d_in, const int* in_sizes, int n_in,
                              void* d_out, int out_size) {
    const float* x_patient = (const float*)d_in[0];
    const float* x_concept = (const float*)d_in[1];
    const float* W_p    = (const float*)d_in[2];
    const float* b_p    = (const float*)d_in[3];
    const float* W_c    = (const float*)d_in[4];
    const float* b_c    = (const float*)d_in[5];
    const float* W_root = (const float*)d_in[6];
    const float* b_root = (const float*)d_in[7];
    const float* W_rel  = (const float*)d_in[8];
    const int* src_pc = (const int*)d_in[9];
    const int* dst_pc = (const int*)d_in[10];
    const int* src_cp = (const int*)d_in[11];
    const int* dst_cp = (const int*)d_in[12];
    float* out = (float*)d_out;

    float *rcnt;
    __half *h0, *h1, *agg16, *Bg16, *Bp16, *Bc16;
    int *deg, *off, *cur, *csr;
    cudaGetSymbolAddress((void**)&h0,    g_h0);
    cudaGetSymbolAddress((void**)&h1,    g_h1);
    cudaGetSymbolAddress((void**)&agg16, g_agg16);
    cudaGetSymbolAddress((void**)&rcnt,  g_rcnt);
    cudaGetSymbolAddress((void**)&deg,   g_deg);
    cudaGetSymbolAddress((void**)&off,   g_off);
    cudaGetSymbolAddress((void**)&cur,   g_cur);
    cudaGetSymbolAddress((void**)&csr,   g_csr);
    cudaGetSymbolAddress((void**)&Bg16,  g_B16);
    cudaGetSymbolAddress((void**)&Bp16,  g_Bp16);
    cudaGetSymbolAddress((void**)&Bc16,  g_Bc16);

    const int LAYER_SMEM = SM_WORDS * 4;                 // 27648 B
    cudaFuncSetAttribute(proj_mma_kernel<2>, cudaFuncAttributeMaxDynamicSharedMemorySize, LAYER_SMEM);
    cudaFuncSetAttribute(proj_mma_kernel<4>, cudaFuncAttributeMaxDynamicSharedMemorySize, LAYER_SMEM);
    cudaFuncSetAttribute(layer_mma_kernel<false>, cudaFuncAttributeMaxDynamicSharedMemorySize, LAYER_SMEM);
    cudaFuncSetAttribute(layer_mma_kernel<true>,  cudaFuncAttributeMaxDynamicSharedMemorySize, LAYER_SMEM);

    // ---- side stream + fork/join events (created once; capturable pattern) ----
    static cudaStream_t s_side = nullptr;
    static cudaEvent_t  ev_fork = nullptr, ev_join = nullptr;
    if (s_side == nullptr) {
        cudaStreamCreateWithFlags(&s_side, cudaStreamNonBlocking);
        cudaEventCreateWithFlags(&ev_fork, cudaEventDisableTiming);
        cudaEventCreateWithFlags(&ev_join, cudaEventDisableTiming);
    }

    // fork
    cudaEventRecord(ev_fork, 0);
    cudaStreamWaitEvent(s_side, ev_fork, 0);

    // ---- side stream: weight prep + projections (independent of CSR build) ----
    prepB_kernel<<<(155648 + 255) / 256, 256, 0, s_side>>>(W_root, W_rel, W_p, W_c,
                                                           Bg16, Bp16, Bc16);
    proj_mma_kernel<2><<<(NPAT + 127) / 128, 256, LAYER_SMEM, s_side>>>(
        x_patient, Bp16, b_p, h0, NPAT);
    proj_mma_kernel<4><<<(NCON + 127) / 128, 256, LAYER_SMEM, s_side>>>(
        x_concept, Bc16, b_c, h0 + (size_t)NPAT * HH, NCON);
    cudaEventRecord(ev_join, s_side);

    // ---- main stream: CSR build ----
    cudaMemsetAsync(deg, 0, NN * sizeof(int));
    deg_kernel<<<(2 * EE + 255) / 256, 256>>>(dst_pc, dst_cp, deg);
    scan_kernel<<<1, 1024>>>(deg, off, rcnt, cur);
    fill_kernel<<<(2 * EE + 255) / 256, 256>>>(src_pc, dst_pc, src_cp, dst_cp, off, cur, csr);

    // join
    cudaStreamWaitEvent(0, ev_join, 0);

    const int NB_TC = (NPAT + 127) / 128 + (NCON + 127) / 128;  // 548
    const int GATHER_BLOCKS = (NN + 7) / 8;

    // ---- layer 0 (fp16 out) ----
    gather_kernel<<<GATHER_BLOCKS, 256>>>(h0, off, csr, rcnt, agg16);
    layer_mma_kernel<false><<<NB_TC, 256, LAYER_SMEM>>>(h0, agg16, Bg16, b_root,
                                                        (float*)nullptr, h1, 0);
    // ---- layer 1 (fp32 out) ----
    gather_kernel<<<GATHER_BLOCKS, 256>>>(h1, off, csr, rcnt, agg16);
    layer_mma_kernel<true><<<NB_TC, 256, LAYER_SMEM>>>(h1, agg16, Bg16, b_root + HH,
                                                       out, (__half*)nullptr, 1);
}

// round 16
// speedup vs baseline: 1.2296x; 1.2296x over previous
#include <cuda_runtime.h>
#include <cuda_fp16.h>
#include <cstdint>

#define NPAT 50000
#define NCON 20000
#define NN   70000
#define EE   800000
#define HH   128
#define LL   2

// ---------------- scratch (static device globals; no allocs allowed) ----------------
__device__ __half g_h0   [(size_t)NN * HH];   // proj output / layer-0 input
__device__ __half g_h1   [(size_t)NN * HH];   // layer-0 output / layer-1 input
__device__ __half g_agg16[(size_t)NN * HH];   // neighbor mean (fp32 accum, fp16 store)
__device__ int    g_deg [NN];
__device__ float  g_rcnt[NN];
__device__ int    g_off [NN + 1];
__device__ int    g_cur [NN];
__device__ int    g_csr [2 * EE];
// fp16 hi/lo split weights, half2-packed along k.
// Layer variant v occupies halves [v*65536, v*65536+32768) = hi, [+32768, +65536) = lo.
__device__ __half g_B16[(size_t)8 * 128 * 128 * 2];   // 4 variants x (hi+lo) x 32768
__device__ __half g_Bp16[2 * 64 * 128];               // W_p hi/lo (K=64)
__device__ __half g_Bc16[2 * 128 * 128];              // W_c hi/lo (K=128)

// ---------------- helpers ----------------
__device__ __forceinline__ void mma_f16(float* c, const uint32_t* a, const uint32_t* b) {
    asm volatile(
        "mma.sync.aligned.m16n8k16.row.col.f32.f16.f16.f32 "
        "{%0,%1,%2,%3}, {%4,%5,%6,%7}, {%8,%9}, {%0,%1,%2,%3};"
        : "+f"(c[0]), "+f"(c[1]), "+f"(c[2]), "+f"(c[3])
        : "r"(a[0]), "r"(a[1]), "r"(a[2]), "r"(a[3]),
          "r"(b[0]), "r"(b[1]));
}

// ---------------- degree histogram ----------------
__global__ void deg_kernel(const int* __restrict__ dst_pc, const int* __restrict__ dst_cp,
                           int* __restrict__ deg) {
    int i = blockIdx.x * blockDim.x + threadIdx.x;
    if (i < EE)               atomicAdd(&deg[NPAT + dst_pc[i]], 1);
    else if (i < 2 * EE)      atomicAdd(&deg[dst_cp[i - EE]], 1);
}

__global__ void rcnt_kernel(const int* __restrict__ deg, float* __restrict__ rcnt) {
    int i = blockIdx.x * blockDim.x + threadIdx.x;
    if (i < NN) rcnt[i] = 1.0f / (float)max(deg[i], 1);
}

// ---------------- single-block exclusive scan ----------------
__global__ void scan_kernel(const int* __restrict__ deg, int* __restrict__ off) {
    __shared__ int ssum[1024];
    int tid = threadIdx.x;
    const int PER = (NN + 1023) / 1024;
    int base = tid * PER;
    int s = 0;
    for (int i = 0; i < PER; i++) { int idx = base + i; if (idx < NN) s += deg[idx]; }
    ssum[tid] = s;
    __syncthreads();
    for (int ofs = 1; ofs < 1024; ofs <<= 1) {
        int v = (tid >= ofs) ? ssum[tid - ofs] : 0;
        __syncthreads();
        ssum[tid] += v;
        __syncthreads();
    }
    int run = (tid == 0) ? 0 : ssum[tid - 1];
    for (int i = 0; i < PER; i++) {
        int idx = base + i;
        if (idx < NN) { off[idx] = run; run += deg[idx]; }
    }
    if (tid == 0) off[NN] = ssum[1023];
}

// ---------------- CSR fill ----------------
__global__ void fill_kernel(const int* __restrict__ src_pc, const int* __restrict__ dst_pc,
                            const int* __restrict__ src_cp, const int* __restrict__ dst_cp,
                            const int* __restrict__ off, int* __restrict__ cur,
                            int* __restrict__ csr) {
    int i = blockIdx.x * blockDim.x + threadIdx.x;
    int s, d;
    if (i < EE)          { s = src_pc[i];             d = NPAT + dst_pc[i]; }
    else if (i < 2 * EE) { s = NPAT + src_cp[i - EE]; d = dst_cp[i - EE]; }
    else return;
    int pos = off[d] + atomicAdd(&cur[d], 1);
    csr[pos] = s;
}

// ---------------- fp16 gather-aggregate (fp32 accumulate, fp16 store) ---------------
__global__ void gather_kernel(const __half* __restrict__ X16,
                              const int* __restrict__ off, const int* __restrict__ csr,
                              const float* __restrict__ rcnt, __half* __restrict__ AGG16) {
    int warp = (int)((blockIdx.x * (long long)blockDim.x + threadIdx.x) >> 5);
    if (warp >= NN) return;
    int lane = threadIdx.x & 31;
    int beg = off[warp], end = off[warp + 1];
    float4 acc = make_float4(0.f, 0.f, 0.f, 0.f);
    int e = beg;
    for (; e + 32 <= end; e += 32) {
        int idx = csr[e + lane];
#pragma unroll
        for (int j = 0; j < 32; j++) {
            int s = __shfl_sync(0xffffffffu, idx, j);
            uint2 u = ((const uint2*)(X16 + (size_t)s * HH))[lane];
            float2 f0 = __half22float2(*(__half2*)&u.x);
            float2 f1 = __half22float2(*(__half2*)&u.y);
            acc.x += f0.x; acc.y += f0.y; acc.z += f1.x; acc.w += f1.y;
        }
    }
    int rem = end - e;
    if (rem > 0) {
        int idx = (lane < rem) ? csr[e + lane] : 0;
        for (int j = 0; j < rem; j++) {
            int s = __shfl_sync(0xffffffffu, idx, j);
            uint2 u = ((const uint2*)(X16 + (size_t)s * HH))[lane];
            float2 f0 = __half22float2(*(__half2*)&u.x);
            float2 f1 = __half22float2(*(__half2*)&u.y);
            acc.x += f0.x; acc.y += f0.y; acc.z += f1.x; acc.w += f1.y;
        }
    }
    float rc = rcnt[warp];
    uint2 o;
    *(__half2*)&o.x = __floats2half2_rn(acc.x * rc, acc.y * rc);
    *(__half2*)&o.y = __floats2half2_rn(acc.z * rc, acc.w * rc);
    ((uint2*)(AGG16 + (size_t)warp * HH))[lane] = o;
}

// ---------------- weight prep: fp16 hi/lo split, half2-packed along k ---------------
// ranges: [0,131072) layer variants; [131072,139264) W_p; [139264,155648) W_c
__global__ void prepB_kernel(const float* __restrict__ W_root, const float* __restrict__ W_rel,
                             const float* __restrict__ W_p, const float* __restrict__ W_c,
                             __half* __restrict__ B16, __half* __restrict__ Bp16,
                             __half* __restrict__ Bc16) {
    int i = blockIdx.x * blockDim.x + threadIdx.x;
    float val; int k, n;
    __half* dst; size_t stride_split;
    if (i < 131072) {
        int v = i >> 15, rem = i & 32767;
        k = rem >> 7; n = rem & 127;
        int l = v >> 1, type = v & 1;
        if (k < 128) val = W_root[((size_t)l * 128 + k) * 128 + n];
        else {
            int rel = (type == 0) ? 1 : 0;
            val = W_rel[(((size_t)l * 2 + rel) * 128 + (k - 128)) * 128 + n];
        }
        dst = B16 + (size_t)v * 65536;
        stride_split = 32768;
    } else if (i < 139264) {
        int rem = i - 131072;
        k = rem >> 7; n = rem & 127;
        val = W_p[k * 128 + n];
        dst = Bp16;
        stride_split = 8192;
    } else if (i < 155648) {
        int rem = i - 139264;
        k = rem >> 7; n = rem & 127;
        val = W_c[k * 128 + n];
        dst = Bc16;
        stride_split = 16384;
    } else return;
    __half hi = __float2half_rn(val);
    float lo = val - __half2float(hi);
    __half lo16 = __float2half_rn(lo);
    int k2 = k >> 1, kb = k & 1;
    size_t idx = ((size_t)k2 * 128 + n) * 2 + kb;
    dst[idx] = hi;
    dst[stride_split + idx] = lo16;
}

// ---------------- shared mma-tile smem layout ---------------------------------------
#define ASTR20  20
#define BSTR136 136
#define SM_A    0
#define SM_BH   (128 * ASTR20)                       // 2560
#define SM_BL   (128 * ASTR20 + 16 * BSTR136)        // 4736
#define SM_WORDS (128 * ASTR20 + 2 * 16 * BSTR136)   // 6912 words = 27648 B

// ---------------- projection MMA: CH[M,128] = fp16(A[M,K] @ W + b) -------------------
template <int KCH>
__global__ void __launch_bounds__(256, 2)
proj_mma_kernel(const float* __restrict__ A, const __half* __restrict__ Bsp,
                const float* __restrict__ bias, __half* __restrict__ CH, int M) {
    extern __shared__ uint32_t smu[];
    int tid = threadIdx.x, wid = tid >> 5, lane = tid & 31;
    int warpM = wid & 3, warpN = wid >> 2;
    int gid = lane >> 2, tig = lane & 3;
    const int K = KCH * 32;
    const int SPLIT_HALVES = KCH * 32 * 128;

    float acc[2][8][4];
#pragma unroll
    for (int mt = 0; mt < 2; mt++)
#pragma unroll
        for (int nt = 0; nt < 8; nt++)
#pragma unroll
            for (int r = 0; r < 4; r++) acc[mt][nt][r] = 0.f;

    int arow = tid >> 1;
    int lr = blockIdx.x * 128 + arow;
    bool valid = lr < M;
    int f4base = (tid & 1) * 4;

    const uint4* bh4 = (const uint4*)(Bsp);
    const uint4* bl4 = (const uint4*)(Bsp + SPLIT_HALVES);

#pragma unroll
    for (int chunk = 0; chunk < KCH; chunk++) {
        const float4* src4 = (const float4*)(A + (size_t)lr * K + chunk * 32);
#pragma unroll
        for (int i = 0; i < 4; i++) {
            int f4 = f4base + i;
            float4 a = valid ? src4[f4] : make_float4(0.f, 0.f, 0.f, 0.f);
            uint2 u;
            *(__half2*)&u.x = __floats2half2_rn(a.x, a.y);
            *(__half2*)&u.y = __floats2half2_rn(a.z, a.w);
            *(uint2*)&smu[SM_A + arow * ASTR20 + f4 * 2] = u;
        }
        {
            int gbase = chunk * 16 * 32;
#pragma unroll
            for (int i = 0; i < 2; i++) {
                int e = tid + 256 * i;
                int k2 = e >> 5, n4 = e & 31;
                uint4 uh = bh4[gbase + e];
                uint4 ul = bl4[gbase + e];
                *(uint4*)&smu[SM_BH + k2 * BSTR136 + n4 * 4] = uh;
                *(uint4*)&smu[SM_BL + k2 * BSTR136 + n4 * 4] = ul;
            }
        }
        __syncthreads();

#pragma unroll
        for (int step = 0; step < 2; step++) {
            int s8 = step * 8;
            uint32_t a[2][4];
#pragma unroll
            for (int mt = 0; mt < 2; mt++) {
                int r0 = warpM * 32 + mt * 16 + gid;
                a[mt][0] = smu[SM_A + r0 * ASTR20 + s8 + tig];
                a[mt][1] = smu[SM_A + (r0 + 8) * ASTR20 + s8 + tig];
                a[mt][2] = smu[SM_A + r0 * ASTR20 + s8 + 4 + tig];
                a[mt][3] = smu[SM_A + (r0 + 8) * ASTR20 + s8 + 4 + tig];
            }
#pragma unroll
            for (int nt = 0; nt < 8; nt++) {
                int n = warpN * 64 + nt * 8 + gid;
                uint32_t bh[2], bl[2];
                bh[0] = smu[SM_BH + (s8 + tig) * BSTR136 + n];
                bh[1] = smu[SM_BH + (s8 + 4 + tig) * BSTR136 + n];
                bl[0] = smu[SM_BL + (s8 + tig) * BSTR136 + n];
                bl[1] = smu[SM_BL + (s8 + 4 + tig) * BSTR136 + n];
#pragma unroll
                for (int mt = 0; mt < 2; mt++) {
                    mma_f16(acc[mt][nt], a[mt], bh);
                    mma_f16(acc[mt][nt], a[mt], bl);
                }
            }
        }
        __syncthreads();
    }

#pragma unroll
    for (int mt = 0; mt < 2; mt++) {
        int row = blockIdx.x * 128 + warpM * 32 + mt * 16 + gid;
#pragma unroll
        for (int nt = 0; nt < 8; nt++) {
            int col = warpN * 64 + nt * 8 + tig * 2;
            float2 bv = *(const float2*)&bias[col];
            if (row < M)
                *(__half2*)&CH[(size_t)row * HH + col] =
                    __floats2half2_rn(acc[mt][nt][0] + bv.x, acc[mt][nt][1] + bv.y);
            if (row + 8 < M)
                *(__half2*)&CH[(size_t)(row + 8) * HH + col] =
                    __floats2half2_rn(acc[mt][nt][2] + bv.x, acc[mt][nt][3] + bv.y);
        }
    }
}

// ---------------- mma.sync fp16 layer with register-staged prefetch -----------------
// out = relu([x|agg] @ (Bhi+Blo) + b). Chunk c+1's A/B global loads are issued into
// registers before the barrier, overlapping the MMA phase; stored to smem next iter.
template <bool FINAL>
__global__ void __launch_bounds__(256, 2)
layer_mma_kernel(const __half* __restrict__ X16, const __half* __restrict__ AGG16,
                 const __half* __restrict__ B16, const float* __restrict__ bias,
                 float* __restrict__ C, __half* __restrict__ CH, int layer) {
    extern __shared__ uint32_t smu[];
    int tid = threadIdx.x, wid = tid >> 5, lane = tid & 31;
    int warpM = wid & 3, warpN = wid >> 2;
    int gid = lane >> 2, tig = lane & 3;

    const int NBP_T = (NPAT + 127) / 128;   // 391
    int bid = blockIdx.x;
    int base, rowlim, v;
    if (bid < NBP_T) { base = bid * 128;                  rowlim = NPAT; v = layer * 2; }
    else             { base = NPAT + (bid - NBP_T) * 128; rowlim = NN;   v = layer * 2 + 1; }

    float acc[2][8][4];
#pragma unroll
    for (int mt = 0; mt < 2; mt++)
#pragma unroll
        for (int nt = 0; nt < 8; nt++)
#pragma unroll
            for (int r = 0; r < 4; r++) acc[mt][nt][r] = 0.f;

    int arow = tid >> 1;
    int node = base + arow;
    bool valid = node < rowlim;
    int f4base = (tid & 1) * 4;

    const uint4* bh4 = (const uint4*)(B16 + (size_t)v * 65536);
    const uint4* bl4 = (const uint4*)(B16 + (size_t)v * 65536 + 32768);

    // B smem target offsets (word units), fixed per thread
    uint32_t bo[2];
#pragma unroll
    for (int i = 0; i < 2; i++) {
        int e = tid + 256 * i;
        int k2 = e >> 5, n4 = e & 31;
        bo[i] = k2 * BSTR136 + n4 * 4;
    }

    // ---- prologue: stage chunk 0 ----
    uint2 sa[4];
    uint4 sbh[2], sbl[2];
    {
        const __half* src = X16 + (size_t)node * HH;
#pragma unroll
        for (int i = 0; i < 4; i++)
            sa[i] = valid ? ((const uint2*)src)[f4base + i] : make_uint2(0u, 0u);
#pragma unroll
        for (int i = 0; i < 2; i++) {
            int e = tid + 256 * i;
            sbh[i] = bh4[e];
            sbl[i] = bl4[e];
        }
    }

    for (int chunk = 0; chunk < 8; chunk++) {
        // ---- store staged chunk to smem ----
#pragma unroll
        for (int i = 0; i < 4; i++)
            *(uint2*)&smu[SM_A + arow * ASTR20 + (f4base + i) * 2] = sa[i];
#pragma unroll
        for (int i = 0; i < 2; i++) {
            *(uint4*)&smu[SM_BH + bo[i]] = sbh[i];
            *(uint4*)&smu[SM_BL + bo[i]] = sbl[i];
        }
        // ---- issue next chunk's global loads (land during MMA phase) ----
        if (chunk < 7) {
            int nc = chunk + 1;
            const __half* nsrc = (nc < 4)
                ? (X16   + (size_t)node * HH + nc * 32)
                : (AGG16 + (size_t)node * HH + (nc - 4) * 32);
#pragma unroll
            for (int i = 0; i < 4; i++)
                sa[i] = valid ? ((const uint2*)nsrc)[f4base + i] : make_uint2(0u, 0u);
            int gbase = nc * 512;
#pragma unroll
            for (int i = 0; i < 2; i++) {
                int e = tid + 256 * i;
                sbh[i] = bh4[gbase + e];
                sbl[i] = bl4[gbase + e];
            }
        }
        __syncthreads();

#pragma unroll
        for (int step = 0; step < 2; step++) {
            int s8 = step * 8;
            uint32_t a[2][4];
#pragma unroll
            for (int mt = 0; mt < 2; mt++) {
                int r0 = warpM * 32 + mt * 16 + gid;
                a[mt][0] = smu[SM_A + r0 * ASTR20 + s8 + tig];
                a[mt][1] = smu[SM_A + (r0 + 8) * ASTR20 + s8 + tig];
                a[mt][2] = smu[SM_A + r0 * ASTR20 + s8 + 4 + tig];
                a[mt][3] = smu[SM_A + (r0 + 8) * ASTR20 + s8 + 4 + tig];
            }
#pragma unroll
            for (int nt = 0; nt < 8; nt++) {
                int n = warpN * 64 + nt * 8 + gid;
                uint32_t bh[2], bl[2];
                bh[0] = smu[SM_BH + (s8 + tig) * BSTR136 + n];
                bh[1] = smu[SM_BH + (s8 + 4 + tig) * BSTR136 + n];
                bl[0] = smu[SM_BL + (s8 + tig) * BSTR136 + n];
                bl[1] = smu[SM_BL + (s8 + 4 + tig) * BSTR136 + n];
#pragma unroll
                for (int mt = 0; mt < 2; mt++) {
                    mma_f16(acc[mt][nt], a[mt], bh);
                    mma_f16(acc[mt][nt], a[mt], bl);
                }
            }
        }
        __syncthreads();
    }

#pragma unroll
    for (int mt = 0; mt < 2; mt++) {
        int row = base + warpM * 32 + mt * 16 + gid;
#pragma unroll
        for (int nt = 0; nt < 8; nt++) {
            int col = warpN * 64 + nt * 8 + tig * 2;
            float2 bv = *(const float2*)&bias[col];
            if (row < rowlim) {
                float2 o;
                o.x = fmaxf(acc[mt][nt][0] + bv.x, 0.f);
                o.y = fmaxf(acc[mt][nt][1] + bv.y, 0.f);
                if (FINAL) *(float2*)&C[(size_t)row * HH + col] = o;
                else       *(__half2*)&CH[(size_t)row * HH + col] = __floats2half2_rn(o.x, o.y);
            }
            if (row + 8 < rowlim) {
                float2 o;
                o.x = fmaxf(acc[mt][nt][2] + bv.x, 0.f);
                o.y = fmaxf(acc[mt][nt][3] + bv.y, 0.f);
                if (FINAL) *(float2*)&C[(size_t)(row + 8) * HH + col] = o;
                else       *(__half2*)&CH[(size_t)(row + 8) * HH + col] = __floats2half2_rn(o.x, o.y);
            }
        }
    }
}

// ---------------- launch (single stream, r14 structure) ------------------------------
extern "C" void kernel_launch(void* const* d_in, const int* in_sizes, int n_in,
                              void* d_out, int out_size) {
    const float* x_patient = (const float*)d_in[0];
    const float* x_concept = (const float*)d_in[1];
    const float* W_p    = (const float*)d_in[2];
    const float* b_p    = (const float*)d_in[3];
    const float* W_c    = (const float*)d_in[4];
    const float* b_c    = (const float*)d_in[5];
    const float* W_root = (const float*)d_in[6];
    const float* b_root = (const float*)d_in[7];
    const float* W_rel  = (const float*)d_in[8];
    const int* src_pc = (const int*)d_in[9];
    const int* dst_pc = (const int*)d_in[10];
    const int* src_cp = (const int*)d_in[11];
    const int* dst_cp = (const int*)d_in[12];
    float* out = (float*)d_out;

    float *rcnt;
    __half *h0, *h1, *agg16, *Bg16, *Bp16, *Bc16;
    int *deg, *off, *cur, *csr;
    cudaGetSymbolAddress((void**)&h0,    g_h0);
    cudaGetSymbolAddress((void**)&h1,    g_h1);
    cudaGetSymbolAddress((void**)&agg16, g_agg16);
    cudaGetSymbolAddress((void**)&rcnt,  g_rcnt);
    cudaGetSymbolAddress((void**)&deg,   g_deg);
    cudaGetSymbolAddress((void**)&off,   g_off);
    cudaGetSymbolAddress((void**)&cur,   g_cur);
    cudaGetSymbolAddress((void**)&csr,   g_csr);
    cudaGetSymbolAddress((void**)&Bg16,  g_B16);
    cudaGetSymbolAddress((void**)&Bp16,  g_Bp16);
    cudaGetSymbolAddress((void**)&Bc16,  g_Bc16);

    const int LAYER_SMEM = SM_WORDS * 4;                 // 27648 B
    cudaFuncSetAttribute(proj_mma_kernel<2>, cudaFuncAttributeMaxDynamicSharedMemorySize, LAYER_SMEM);
    cudaFuncSetAttribute(proj_mma_kernel<4>, cudaFuncAttributeMaxDynamicSharedMemorySize, LAYER_SMEM);
    cudaFuncSetAttribute(layer_mma_kernel<false>, cudaFuncAttributeMaxDynamicSharedMemorySize, LAYER_SMEM);
    cudaFuncSetAttribute(layer_mma_kernel<true>,  cudaFuncAttributeMaxDynamicSharedMemorySize, LAYER_SMEM);

    // ---- CSR build ----
    cudaMemsetAsync(deg, 0, NN * sizeof(int));
    cudaMemsetAsync(cur, 0, NN * sizeof(int));
    deg_kernel<<<(2 * EE + 255) / 256, 256>>>(dst_pc, dst_cp, deg);
    scan_kernel<<<1, 1024>>>(deg, off);
    rcnt_kernel<<<(NN + 255) / 256, 256>>>(deg, rcnt);
    fill_kernel<<<(2 * EE + 255) / 256, 256>>>(src_pc, dst_pc, src_cp, dst_cp, off, cur, csr);

    // ---- weight prep (layers + projections) ----
    prepB_kernel<<<(155648 + 255) / 256, 256>>>(W_root, W_rel, W_p, W_c, Bg16, Bp16, Bc16);

    // ---- projections (fp16 MMA) ----
    proj_mma_kernel<2><<<(NPAT + 127) / 128, 256, LAYER_SMEM>>>(x_patient, Bp16, b_p, h0, NPAT);
    proj_mma_kernel<4><<<(NCON + 127) / 128, 256, LAYER_SMEM>>>(x_concept, Bc16, b_c,
                                                                h0 + (size_t)NPAT * HH, NCON);

    const int NB_TC = (NPAT + 127) / 128 + (NCON + 127) / 128;  // 548
    const int GATHER_BLOCKS = (NN + 7) / 8;

    // ---- layer 0 (fp16 out) ----
    gather_kernel<<<GATHER_BLOCKS, 256>>>(h0, off, csr, rcnt, agg16);
    layer_mma_kernel<false><<<NB_TC, 256, LAYER_SMEM>>>(h0, agg16, Bg16, b_root,
                                                        (float*)nullptr, h1, 0);
    // ---- layer 1 (fp32 out) ----
    gather_kernel<<<GATHER_BLOCKS, 256>>>(h1, off, csr, rcnt, agg16);
    layer_mma_kernel<true><<<NB_TC, 256, LAYER_SMEM>>>(h1, agg16, Bg16, b_root + HH,
                                                       out, (__half*)nullptr, 1);
}

// round 17
// speedup vs baseline: 1.3460x; 1.0947x over previous
#include <cuda_runtime.h>
#include <cuda_fp16.h>
#include <cstdint>

#define NPAT 50000
#define NCON 20000
#define NN   70000
#define EE   800000
#define HH   128
#define LL   2

// ---------------- scratch (static device globals; no allocs allowed) ----------------
__device__ __half g_h0   [(size_t)NN * HH];   // proj output / layer-0 input
__device__ __half g_h1   [(size_t)NN * HH];   // layer-0 output / layer-1 input
__device__ __half g_agg16[(size_t)NN * HH];   // neighbor mean (fp32 accum, fp16 store)
__device__ int    g_deg [NN];
__device__ float  g_rcnt[NN];
__device__ int    g_off [NN + 1];
__device__ int    g_cur [NN];
__device__ int    g_csr [2 * EE];
// fp16 hi/lo split weights, half2-packed along k (lo kept for possible revert; kernels read hi only).
__device__ __half g_B16[(size_t)8 * 128 * 128 * 2];   // 4 variants x (hi+lo) x 32768
__device__ __half g_Bp16[2 * 64 * 128];               // W_p hi/lo (K=64)
__device__ __half g_Bc16[2 * 128 * 128];              // W_c hi/lo (K=128)

// ---------------- helpers ----------------
__device__ __forceinline__ void mma_f16(float* c, const uint32_t* a, const uint32_t* b) {
    asm volatile(
        "mma.sync.aligned.m16n8k16.row.col.f32.f16.f16.f32 "
        "{%0,%1,%2,%3}, {%4,%5,%6,%7}, {%8,%9}, {%0,%1,%2,%3};"
        : "+f"(c[0]), "+f"(c[1]), "+f"(c[2]), "+f"(c[3])
        : "r"(a[0]), "r"(a[1]), "r"(a[2]), "r"(a[3]),
          "r"(b[0]), "r"(b[1]));
}

// ---------------- degree histogram ----------------
__global__ void deg_kernel(const int* __restrict__ dst_pc, const int* __restrict__ dst_cp,
                           int* __restrict__ deg) {
    int i = blockIdx.x * blockDim.x + threadIdx.x;
    if (i < EE)               atomicAdd(&deg[NPAT + dst_pc[i]], 1);
    else if (i < 2 * EE)      atomicAdd(&deg[dst_cp[i - EE]], 1);
}

__global__ void rcnt_kernel(const int* __restrict__ deg, float* __restrict__ rcnt) {
    int i = blockIdx.x * blockDim.x + threadIdx.x;
    if (i < NN) rcnt[i] = 1.0f / (float)max(deg[i], 1);
}

// ---------------- single-block exclusive scan ----------------
__global__ void scan_kernel(const int* __restrict__ deg, int* __restrict__ off) {
    __shared__ int ssum[1024];
    int tid = threadIdx.x;
    const int PER = (NN + 1023) / 1024;
    int base = tid * PER;
    int s = 0;
    for (int i = 0; i < PER; i++) { int idx = base + i; if (idx < NN) s += deg[idx]; }
    ssum[tid] = s;
    __syncthreads();
    for (int ofs = 1; ofs < 1024; ofs <<= 1) {
        int v = (tid >= ofs) ? ssum[tid - ofs] : 0;
        __syncthreads();
        ssum[tid] += v;
        __syncthreads();
    }
    int run = (tid == 0) ? 0 : ssum[tid - 1];
    for (int i = 0; i < PER; i++) {
        int idx = base + i;
        if (idx < NN) { off[idx] = run; run += deg[idx]; }
    }
    if (tid == 0) off[NN] = ssum[1023];
}

// ---------------- CSR fill ----------------
__global__ void fill_kernel(const int* __restrict__ src_pc, const int* __restrict__ dst_pc,
                            const int* __restrict__ src_cp, const int* __restrict__ dst_cp,
                            const int* __restrict__ off, int* __restrict__ cur,
                            int* __restrict__ csr) {
    int i = blockIdx.x * blockDim.x + threadIdx.x;
    int s, d;
    if (i < EE)          { s = src_pc[i];             d = NPAT + dst_pc[i]; }
    else if (i < 2 * EE) { s = NPAT + src_cp[i - EE]; d = dst_cp[i - EE]; }
    else return;
    int pos = off[d] + atomicAdd(&cur[d], 1);
    csr[pos] = s;
}

// ---------------- fp16 gather-aggregate (fp32 accumulate, fp16 store) ---------------
__global__ void gather_kernel(const __half* __restrict__ X16,
                              const int* __restrict__ off, const int* __restrict__ csr,
                              const float* __restrict__ rcnt, __half* __restrict__ AGG16) {
    int warp = (int)((blockIdx.x * (long long)blockDim.x + threadIdx.x) >> 5);
    if (warp >= NN) return;
    int lane = threadIdx.x & 31;
    int beg = off[warp], end = off[warp + 1];
    float4 acc = make_float4(0.f, 0.f, 0.f, 0.f);
    int e = beg;
    for (; e + 32 <= end; e += 32) {
        int idx = csr[e + lane];
#pragma unroll
        for (int j = 0; j < 32; j++) {
            int s = __shfl_sync(0xffffffffu, idx, j);
            uint2 u = ((const uint2*)(X16 + (size_t)s * HH))[lane];
            float2 f0 = __half22float2(*(__half2*)&u.x);
            float2 f1 = __half22float2(*(__half2*)&u.y);
            acc.x += f0.x; acc.y += f0.y; acc.z += f1.x; acc.w += f1.y;
        }
    }
    int rem = end - e;
    if (rem > 0) {
        int idx = (lane < rem) ? csr[e + lane] : 0;
        for (int j = 0; j < rem; j++) {
            int s = __shfl_sync(0xffffffffu, idx, j);
            uint2 u = ((const uint2*)(X16 + (size_t)s * HH))[lane];
            float2 f0 = __half22float2(*(__half2*)&u.x);
            float2 f1 = __half22float2(*(__half2*)&u.y);
            acc.x += f0.x; acc.y += f0.y; acc.z += f1.x; acc.w += f1.y;
        }
    }
    float rc = rcnt[warp];
    uint2 o;
    *(__half2*)&o.x = __floats2half2_rn(acc.x * rc, acc.y * rc);
    *(__half2*)&o.y = __floats2half2_rn(acc.z * rc, acc.w * rc);
    ((uint2*)(AGG16 + (size_t)warp * HH))[lane] = o;
}

// ---------------- weight prep: fp16 hi/lo split, half2-packed along k ---------------
__global__ void prepB_kernel(const float* __restrict__ W_root, const float* __restrict__ W_rel,
                             const float* __restrict__ W_p, const float* __restrict__ W_c,
                             __half* __restrict__ B16, __half* __restrict__ Bp16,
                             __half* __restrict__ Bc16) {
    int i = blockIdx.x * blockDim.x + threadIdx.x;
    float val; int k, n;
    __half* dst; size_t stride_split;
    if (i < 131072) {
        int v = i >> 15, rem = i & 32767;
        k = rem >> 7; n = rem & 127;
        int l = v >> 1, type = v & 1;
        if (k < 128) val = W_root[((size_t)l * 128 + k) * 128 + n];
        else {
            int rel = (type == 0) ? 1 : 0;
            val = W_rel[(((size_t)l * 2 + rel) * 128 + (k - 128)) * 128 + n];
        }
        dst = B16 + (size_t)v * 65536;
        stride_split = 32768;
    } else if (i < 139264) {
        int rem = i - 131072;
        k = rem >> 7; n = rem & 127;
        val = W_p[k * 128 + n];
        dst = Bp16;
        stride_split = 8192;
    } else if (i < 155648) {
        int rem = i - 139264;
        k = rem >> 7; n = rem & 127;
        val = W_c[k * 128 + n];
        dst = Bc16;
        stride_split = 16384;
    } else return;
    __half hi = __float2half_rn(val);
    float lo = val - __half2float(hi);
    __half lo16 = __float2half_rn(lo);
    int k2 = k >> 1, kb = k & 1;
    size_t idx = ((size_t)k2 * 128 + n) * 2 + kb;
    dst[idx] = hi;
    dst[stride_split + idx] = lo16;
}

// ---------------- shared mma-tile smem layout (hi-only B) ---------------------------
#define ASTR20  20
#define BSTR136 136
#define SM_A    0
#define SM_BH   (128 * ASTR20)                       // 2560
#define SM_WORDS (128 * ASTR20 + 16 * BSTR136)       // 4736 words = 18944 B

// ---------------- projection MMA: CH[M,128] = fp16(A[M,K] @ W + b) -------------------
template <int KCH>
__global__ void __launch_bounds__(256, 2)
proj_mma_kernel(const float* __restrict__ A, const __half* __restrict__ Bsp,
                const float* __restrict__ bias, __half* __restrict__ CH, int M) {
    extern __shared__ uint32_t smu[];
    int tid = threadIdx.x, wid = tid >> 5, lane = tid & 31;
    int warpM = wid & 3, warpN = wid >> 2;
    int gid = lane >> 2, tig = lane & 3;
    const int K = KCH * 32;

    float acc[2][8][4];
#pragma unroll
    for (int mt = 0; mt < 2; mt++)
#pragma unroll
        for (int nt = 0; nt < 8; nt++)
#pragma unroll
            for (int r = 0; r < 4; r++) acc[mt][nt][r] = 0.f;

    int arow = tid >> 1;
    int lr = blockIdx.x * 128 + arow;
    bool valid = lr < M;
    int f4base = (tid & 1) * 4;

    const uint4* bh4 = (const uint4*)(Bsp);   // hi split only

#pragma unroll
    for (int chunk = 0; chunk < KCH; chunk++) {
        const float4* src4 = (const float4*)(A + (size_t)lr * K + chunk * 32);
#pragma unroll
        for (int i = 0; i < 4; i++) {
            int f4 = f4base + i;
            float4 a = valid ? src4[f4] : make_float4(0.f, 0.f, 0.f, 0.f);
            uint2 u;
            *(__half2*)&u.x = __floats2half2_rn(a.x, a.y);
            *(__half2*)&u.y = __floats2half2_rn(a.z, a.w);
            *(uint2*)&smu[SM_A + arow * ASTR20 + f4 * 2] = u;
        }
        {
            int gbase = chunk * 16 * 32;
#pragma unroll
            for (int i = 0; i < 2; i++) {
                int e = tid + 256 * i;
                int k2 = e >> 5, n4 = e & 31;
                *(uint4*)&smu[SM_BH + k2 * BSTR136 + n4 * 4] = bh4[gbase + e];
            }
        }
        __syncthreads();

#pragma unroll
        for (int step = 0; step < 2; step++) {
            int s8 = step * 8;
            uint32_t a[2][4];
#pragma unroll
            for (int mt = 0; mt < 2; mt++) {
                int r0 = warpM * 32 + mt * 16 + gid;
                a[mt][0] = smu[SM_A + r0 * ASTR20 + s8 + tig];
                a[mt][1] = smu[SM_A + (r0 + 8) * ASTR20 + s8 + tig];
                a[mt][2] = smu[SM_A + r0 * ASTR20 + s8 + 4 + tig];
                a[mt][3] = smu[SM_A + (r0 + 8) * ASTR20 + s8 + 4 + tig];
            }
#pragma unroll
            for (int nt = 0; nt < 8; nt++) {
                int n = warpN * 64 + nt * 8 + gid;
                uint32_t bh[2];
                bh[0] = smu[SM_BH + (s8 + tig) * BSTR136 + n];
                bh[1] = smu[SM_BH + (s8 + 4 + tig) * BSTR136 + n];
#pragma unroll
                for (int mt = 0; mt < 2; mt++)
                    mma_f16(acc[mt][nt], a[mt], bh);
            }
        }
        __syncthreads();
    }

#pragma unroll
    for (int mt = 0; mt < 2; mt++) {
        int row = blockIdx.x * 128 + warpM * 32 + mt * 16 + gid;
#pragma unroll
        for (int nt = 0; nt < 8; nt++) {
            int col = warpN * 64 + nt * 8 + tig * 2;
            float2 bv = *(const float2*)&bias[col];
            if (row < M)
                *(__half2*)&CH[(size_t)row * HH + col] =
                    __floats2half2_rn(acc[mt][nt][0] + bv.x, acc[mt][nt][1] + bv.y);
            if (row + 8 < M)
                *(__half2*)&CH[(size_t)(row + 8) * HH + col] =
                    __floats2half2_rn(acc[mt][nt][2] + bv.x, acc[mt][nt][3] + bv.y);
        }
    }
}

// ---------------- mma.sync fp16 layer (hi-only B, register-staged prefetch) ----------
template <bool FINAL>
__global__ void __launch_bounds__(256, 2)
layer_mma_kernel(const __half* __restrict__ X16, const __half* __restrict__ AGG16,
                 const __half* __restrict__ B16, const float* __restrict__ bias,
                 float* __restrict__ C, __half* __restrict__ CH, int layer) {
    extern __shared__ uint32_t smu[];
    int tid = threadIdx.x, wid = tid >> 5, lane = tid & 31;
    int warpM = wid & 3, warpN = wid >> 2;
    int gid = lane >> 2, tig = lane & 3;

    const int NBP_T = (NPAT + 127) / 128;   // 391
    int bid = blockIdx.x;
    int base, rowlim, v;
    if (bid < NBP_T) { base = bid * 128;                  rowlim = NPAT; v = layer * 2; }
    else             { base = NPAT + (bid - NBP_T) * 128; rowlim = NN;   v = layer * 2 + 1; }

    float acc[2][8][4];
#pragma unroll
    for (int mt = 0; mt < 2; mt++)
#pragma unroll
        for (int nt = 0; nt < 8; nt++)
#pragma unroll
            for (int r = 0; r < 4; r++) acc[mt][nt][r] = 0.f;

    int arow = tid >> 1;
    int node = base + arow;
    bool valid = node < rowlim;
    int f4base = (tid & 1) * 4;

    const uint4* bh4 = (const uint4*)(B16 + (size_t)v * 65536);   // hi split only

    uint32_t bo[2];
#pragma unroll
    for (int i = 0; i < 2; i++) {
        int e = tid + 256 * i;
        int k2 = e >> 5, n4 = e & 31;
        bo[i] = k2 * BSTR136 + n4 * 4;
    }

    // ---- prologue: stage chunk 0 ----
    uint2 sa[4];
    uint4 sbh[2];
    {
        const __half* src = X16 + (size_t)node * HH;
#pragma unroll
        for (int i = 0; i < 4; i++)
            sa[i] = valid ? ((const uint2*)src)[f4base + i] : make_uint2(0u, 0u);
#pragma unroll
        for (int i = 0; i < 2; i++)
            sbh[i] = bh4[tid + 256 * i];
    }

    for (int chunk = 0; chunk < 8; chunk++) {
        // ---- store staged chunk to smem ----
#pragma unroll
        for (int i = 0; i < 4; i++)
            *(uint2*)&smu[SM_A + arow * ASTR20 + (f4base + i) * 2] = sa[i];
#pragma unroll
        for (int i = 0; i < 2; i++)
            *(uint4*)&smu[SM_BH + bo[i]] = sbh[i];
        // ---- issue next chunk's global loads (land during MMA phase) ----
        if (chunk < 7) {
            int nc = chunk + 1;
            const __half* nsrc = (nc < 4)
                ? (X16   + (size_t)node * HH + nc * 32)
                : (AGG16 + (size_t)node * HH + (nc - 4) * 32);
#pragma unroll
            for (int i = 0; i < 4; i++)
                sa[i] = valid ? ((const uint2*)nsrc)[f4base + i] : make_uint2(0u, 0u);
            int gbase = nc * 512;
#pragma unroll
            for (int i = 0; i < 2; i++)
                sbh[i] = bh4[gbase + tid + 256 * i];
        }
        __syncthreads();

#pragma unroll
        for (int step = 0; step < 2; step++) {
            int s8 = step * 8;
            uint32_t a[2][4];
#pragma unroll
            for (int mt = 0; mt < 2; mt++) {
                int r0 = warpM * 32 + mt * 16 + gid;
                a[mt][0] = smu[SM_A + r0 * ASTR20 + s8 + tig];
                a[mt][1] = smu[SM_A + (r0 + 8) * ASTR20 + s8 + tig];
                a[mt][2] = smu[SM_A + r0 * ASTR20 + s8 + 4 + tig];
                a[mt][3] = smu[SM_A + (r0 + 8) * ASTR20 + s8 + 4 + tig];
            }
#pragma unroll
            for (int nt = 0; nt < 8; nt++) {
                int n = warpN * 64 + nt * 8 + gid;
                uint32_t bh[2];
                bh[0] = smu[SM_BH + (s8 + tig) * BSTR136 + n];
                bh[1] = smu[SM_BH + (s8 + 4 + tig) * BSTR136 + n];
#pragma unroll
                for (int mt = 0; mt < 2; mt++)
                    mma_f16(acc[mt][nt], a[mt], bh);
            }
        }
        __syncthreads();
    }

#pragma unroll
    for (int mt = 0; mt < 2; mt++) {
        int row = base + warpM * 32 + mt * 16 + gid;
#pragma unroll
        for (int nt = 0; nt < 8; nt++) {
            int col = warpN * 64 + nt * 8 + tig * 2;
            float2 bv = *(const float2*)&bias[col];
            if (row < rowlim) {
                float2 o;
                o.x = fmaxf(acc[mt][nt][0] + bv.x, 0.f);
                o.y = fmaxf(acc[mt][nt][1] + bv.y, 0.f);
                if (FINAL) *(float2*)&C[(size_t)row * HH + col] = o;
                else       *(__half2*)&CH[(size_t)row * HH + col] = __floats2half2_rn(o.x, o.y);
            }
            if (row + 8 < rowlim) {
                float2 o;
                o.x = fmaxf(acc[mt][nt][2] + bv.x, 0.f);
                o.y = fmaxf(acc[mt][nt][3] + bv.y, 0.f);
                if (FINAL) *(float2*)&C[(size_t)(row + 8) * HH + col] = o;
                else       *(__half2*)&CH[(size_t)(row + 8) * HH + col] = __floats2half2_rn(o.x, o.y);
            }
        }
    }
}

// ---------------- launch (single stream) --------------------------------------------
extern "C" void kernel_launch(void* const* d_in, const int* in_sizes, int n_in,
                              void* d_out, int out_size) {
    const float* x_patient = (const float*)d_in[0];
    const float* x_concept = (const float*)d_in[1];
    const float* W_p    = (const float*)d_in[2];
    const float* b_p    = (const float*)d_in[3];
    const float* W_c    = (const float*)d_in[4];
    const float* b_c    = (const float*)d_in[5];
    const float* W_root = (const float*)d_in[6];
    const float* b_root = (const float*)d_in[7];
    const float* W_rel  = (const float*)d_in[8];
    const int* src_pc = (const int*)d_in[9];
    const int* dst_pc = (const int*)d_in[10];
    const int* src_cp = (const int*)d_in[11];
    const int* dst_cp = (const int*)d_in[12];
    float* out = (float*)d_out;

    float *rcnt;
    __half *h0, *h1, *agg16, *Bg16, *Bp16, *Bc16;
    int *deg, *off, *cur, *csr;
    cudaGetSymbolAddress((void**)&h0,    g_h0);
    cudaGetSymbolAddress((void**)&h1,    g_h1);
    cudaGetSymbolAddress((void**)&agg16, g_agg16);
    cudaGetSymbolAddress((void**)&rcnt,  g_rcnt);
    cudaGetSymbolAddress((void**)&deg,   g_deg);
    cudaGetSymbolAddress((void**)&off,   g_off);
    cudaGetSymbolAddress((void**)&cur,   g_cur);
    cudaGetSymbolAddress((void**)&csr,   g_csr);
    cudaGetSymbolAddress((void**)&Bg16,  g_B16);
    cudaGetSymbolAddress((void**)&Bp16,  g_Bp16);
    cudaGetSymbolAddress((void**)&Bc16,  g_Bc16);

    const int LAYER_SMEM = SM_WORDS * 4;                 // 18944 B
    cudaFuncSetAttribute(proj_mma_kernel<2>, cudaFuncAttributeMaxDynamicSharedMemorySize, LAYER_SMEM);
    cudaFuncSetAttribute(proj_mma_kernel<4>, cudaFuncAttributeMaxDynamicSharedMemorySize, LAYER_SMEM);
    cudaFuncSetAttribute(layer_mma_kernel<false>, cudaFuncAttributeMaxDynamicSharedMemorySize, LAYER_SMEM);
    cudaFuncSetAttribute(layer_mma_kernel<true>,  cudaFuncAttributeMaxDynamicSharedMemorySize, LAYER_SMEM);

    // ---- CSR build ----
    cudaMemsetAsync(deg, 0, NN * sizeof(int));
    cudaMemsetAsync(cur, 0, NN * sizeof(int));
    deg_kernel<<<(2 * EE + 255) / 256, 256>>>(dst_pc, dst_cp, deg);
    scan_kernel<<<1, 1024>>>(deg, off);
    rcnt_kernel<<<(NN + 255) / 256, 256>>>(deg, rcnt);
    fill_kernel<<<(2 * EE + 255) / 256, 256>>>(src_pc, dst_pc, src_cp, dst_cp, off, cur, csr);

    // ---- weight prep (layers + projections) ----
    prepB_kernel<<<(155648 + 255) / 256, 256>>>(W_root, W_rel, W_p, W_c, Bg16, Bp16, Bc16);

    // ---- projections (fp16 MMA) ----
    proj_mma_kernel<2><<<(NPAT + 127) / 128, 256, LAYER_SMEM>>>(x_patient, Bp16, b_p, h0, NPAT);
    proj_mma_kernel<4><<<(NCON + 127) / 128, 256, LAYER_SMEM>>>(x_concept, Bc16, b_c,
                                                                h0 + (size_t)NPAT * HH, NCON);

    const int NB_TC = (NPAT + 127) / 128 + (NCON + 127) / 128;  // 548
    const int GATHER_BLOCKS = (NN + 7) / 8;

    // ---- layer 0 (fp16 out) ----
    gather_kernel<<<GATHER_BLOCKS, 256>>>(h0, off, csr, rcnt, agg16);
    layer_mma_kernel<false><<<NB_TC, 256, LAYER_SMEM>>>(h0, agg16, Bg16, b_root,
                                                        (float*)nullptr, h1, 0);
    // ---- layer 1 (fp32 out) ----
    gather_kernel<<<GATHER_BLOCKS, 256>>>(h1, off, csr, rcnt, agg16);
    layer_mma_kernel<true><<<NB_TC, 256, LAYER_SMEM>>>(h1, agg16, Bg16, b_root + HH,
                                                       out, (__half*)nullptr, 1);
}